// round 2
// baseline (speedup 1.0000x reference)
#include <cuda_runtime.h>
#include <math.h>

// ---------------- problem constants ----------------
#define B_   2
#define L_   4096
#define DM   2048          // D_MODEL
#define DI   4096          // D_INNER
#define NH   64            // N_HEADS
#define DH   64            // D_HEAD
#define NS   128           // D_STATE
#define CD   4352          // CONV_DIM
#define DPJ  8512          // D_IN_PROJ
#define CK   256           // CHUNK
#define NCH  32            // total chunks = B * (L/CHUNK)
#define RW   8192          // total rows = B*L

// ---------------- scratch (device globals; no allocations) ----------------
__device__ float g_zx[(size_t)RW * DPJ];        // in-proj output
__device__ float g_xBC[(size_t)RW * CD];        // conv+silu output
__device__ float g_dt[RW * NH];                 // softplus(dt)
__device__ float g_dacs[RW * NH];               // cumsum(dt*A) within chunk
__device__ float g_CBt[NCH * CK * CK];          // per-chunk (C@B^T)^T : [j][i]
__device__ float g_states[(size_t)NCH * NH * DH * NS];
__device__ float g_prev[(size_t)NCH * NH * DH * NS];
__device__ float g_y[(size_t)RW * DI];          // y pre-norm, then normalized in place

// ---------------- generic batched NT SGEMM ----------------
// C[m][n] = sum_k A[m][k] * B[n][k]; row-major with strides; M%128==0, K%16==0 assumed.
__global__ __launch_bounds__(256) void sgemm_nt(
    const float* __restrict__ A, const float* __restrict__ Bm, float* __restrict__ C,
    int M, int N, int K, int lda, int ldb, int ldc,
    long sA, long sB, long sC)
{
    const float* Ab = A + (long)blockIdx.z * sA;
    const float* Bb = Bm + (long)blockIdx.z * sB;
    float* Cb = C + (long)blockIdx.z * sC;

    __shared__ float As[16][128];
    __shared__ float Bs[16][128];

    const int tid = threadIdx.x;
    const int m0 = blockIdx.y * 128;
    const int n0 = blockIdx.x * 128;
    const int tx = tid & 15;
    const int ty = tid >> 4;

    const int lrow = tid >> 1;
    const int lk = (tid & 1) * 8;
    const float* Aload = Ab + (long)(m0 + lrow) * lda + lk;
    const float* Bload = Bb + (long)(n0 + lrow) * ldb + lk;
    const bool bvalid = (n0 + lrow) < N;

    float acc[8][8];
#pragma unroll
    for (int i = 0; i < 8; i++)
#pragma unroll
        for (int j = 0; j < 8; j++) acc[i][j] = 0.0f;

    float4 a0 = *(const float4*)(Aload);
    float4 a1 = *(const float4*)(Aload + 4);
    float4 b0 = make_float4(0.f,0.f,0.f,0.f), b1 = make_float4(0.f,0.f,0.f,0.f);
    if (bvalid) { b0 = *(const float4*)(Bload); b1 = *(const float4*)(Bload + 4); }

    for (int k0 = 0; k0 < K; k0 += 16) {
        As[lk+0][lrow] = a0.x; As[lk+1][lrow] = a0.y; As[lk+2][lrow] = a0.z; As[lk+3][lrow] = a0.w;
        As[lk+4][lrow] = a1.x; As[lk+5][lrow] = a1.y; As[lk+6][lrow] = a1.z; As[lk+7][lrow] = a1.w;
        Bs[lk+0][lrow] = b0.x; Bs[lk+1][lrow] = b0.y; Bs[lk+2][lrow] = b0.z; Bs[lk+3][lrow] = b0.w;
        Bs[lk+4][lrow] = b1.x; Bs[lk+5][lrow] = b1.y; Bs[lk+6][lrow] = b1.z; Bs[lk+7][lrow] = b1.w;
        __syncthreads();
        if (k0 + 16 < K) {
            a0 = *(const float4*)(Aload + k0 + 16);
            a1 = *(const float4*)(Aload + k0 + 20);
            if (bvalid) {
                b0 = *(const float4*)(Bload + k0 + 16);
                b1 = *(const float4*)(Bload + k0 + 20);
            }
        }
#pragma unroll
        for (int kk = 0; kk < 16; kk++) {
            float av[8], bv[8];
            *(float4*)&av[0] = *(const float4*)&As[kk][ty*8];
            *(float4*)&av[4] = *(const float4*)&As[kk][ty*8+4];
            *(float4*)&bv[0] = *(const float4*)&Bs[kk][tx*8];
            *(float4*)&bv[4] = *(const float4*)&Bs[kk][tx*8+4];
#pragma unroll
            for (int i = 0; i < 8; i++)
#pragma unroll
                for (int j = 0; j < 8; j++) acc[i][j] += av[i]*bv[j];
        }
        __syncthreads();
    }

#pragma unroll
    for (int i = 0; i < 8; i++) {
        int row = m0 + ty*8 + i;
        float* Crow = Cb + (long)row*ldc + n0 + tx*8;
        if (n0 + tx*8 + 4 <= N) {
            *(float4*)Crow = make_float4(acc[i][0],acc[i][1],acc[i][2],acc[i][3]);
        }
        if (n0 + tx*8 + 8 <= N) {
            *(float4*)(Crow+4) = make_float4(acc[i][4],acc[i][5],acc[i][6],acc[i][7]);
        }
    }
}

// ---------------- causal depthwise conv (width 4) + SiLU ----------------
__global__ void conv_silu_kernel(const float* __restrict__ conv_w,
                                 const float* __restrict__ conv_b)
{
    int cc = blockIdx.x * 256 + threadIdx.x;  // 0..4351
    int r = blockIdx.y;                       // 0..8191
    int l = r & (L_ - 1);
    float acc = conv_b[cc];
    const float* col = g_zx + (size_t)r * DPJ + DI + cc;
#pragma unroll
    for (int w = 0; w < 4; w++) {
        int lp = l - 3 + w;
        if (lp >= 0) acc += col[(long)(w - 3) * DPJ] * conv_w[cc*4 + w];
    }
    float s = acc / (1.0f + __expf(-acc));
    g_xBC[(size_t)r * CD + cc] = s;
}

// ---------------- dt softplus + within-chunk cumsum of dt*A ----------------
__global__ void dt_cumsum_kernel(const float* __restrict__ dt_bias,
                                 const float* __restrict__ A_log)
{
    int h = threadIdx.x;      // 0..63
    int chunk = blockIdx.x;   // 0..31
    int base = chunk * CK;
    float Ah = -expf(A_log[h]);
    float bh = dt_bias[h];
    float acc = 0.f;
    for (int i = 0; i < CK; i++) {
        int r = base + i;
        float x = g_zx[(size_t)r * DPJ + DI + CD + h] + bh;
        float dt = fmaxf(x, 0.f) + log1pf(expf(-fabsf(x)));   // softplus
        g_dt[r*NH + h] = dt;
        acc += dt * Ah;
        g_dacs[r*NH + h] = acc;
    }
}

// ---------------- per-(chunk,head) state accumulation ----------------
// states[p][n] = sum_s exp(dacs_last - dacs[s]) * dt[s] * x[s][p] * B[s][n]
__global__ __launch_bounds__(256) void states_kernel()
{
    int chunk = blockIdx.x;
    int h = blockIdx.y;
    int base = chunk * CK;
    int tid = threadIdx.x;

    __shared__ float ws[CK];
    __shared__ float xs[32*64];
    __shared__ float Bsh[32*128];

    {
        float dl = g_dacs[(base + CK - 1)*NH + h];
        float dv = g_dacs[(base + tid)*NH + h];
        ws[tid] = __expf(dl - dv) * g_dt[(base + tid)*NH + h];
    }

    const int tp = tid >> 5;   // 0..7 (warp id)
    const int tn = tid & 31;   // 0..31
    float acc[8][4];
#pragma unroll
    for (int a = 0; a < 8; a++)
#pragma unroll
        for (int b = 0; b < 4; b++) acc[a][b] = 0.f;

    for (int st = 0; st < 8; st++) {
        __syncthreads();
        // load x tile: 32 rows x 64
#pragma unroll
        for (int rep = 0; rep < 2; rep++) {
            int f = tid + rep*256;       // 0..511 float4 slots
            int row = f >> 4, c4 = f & 15;
            *(float4*)&xs[row*64 + c4*4] =
                *(const float4*)&g_xBC[(size_t)(base + st*32 + row)*CD + h*64 + c4*4];
        }
        // load B tile: 32 rows x 128
#pragma unroll
        for (int rep = 0; rep < 4; rep++) {
            int f = tid + rep*256;       // 0..1023
            int row = f >> 5, c4 = f & 31;
            *(float4*)&Bsh[row*128 + c4*4] =
                *(const float4*)&g_xBC[(size_t)(base + st*32 + row)*CD + DI + c4*4];
        }
        __syncthreads();

        for (int s = 0; s < 32; s++) {
            float w = ws[st*32 + s];
            float4 bv = *(const float4*)&Bsh[s*128 + tn*4];
            float xw[8];
#pragma unroll
            for (int pp = 0; pp < 8; pp++) xw[pp] = w * xs[s*64 + tp + pp*8];
#pragma unroll
            for (int pp = 0; pp < 8; pp++) {
                acc[pp][0] += xw[pp]*bv.x;
                acc[pp][1] += xw[pp]*bv.y;
                acc[pp][2] += xw[pp]*bv.z;
                acc[pp][3] += xw[pp]*bv.w;
            }
        }
    }

    size_t obase = (size_t)(chunk*NH + h) * DH * NS;
#pragma unroll
    for (int pp = 0; pp < 8; pp++) {
        *(float4*)&g_states[obase + (size_t)(tp + pp*8)*NS + tn*4] =
            make_float4(acc[pp][0], acc[pp][1], acc[pp][2], acc[pp][3]);
    }
}

// ---------------- inter-chunk scan (prev = state BEFORE chunk c) ----------------
__global__ void scan_kernel()
{
    int idx = blockIdx.x * 256 + threadIdx.x;   // over 2*64*64*128
    int n = idx & 127;
    int p = (idx >> 7) & 63;
    int h = (idx >> 13) & 63;
    int b = idx >> 19;
    float s = 0.f;
    for (int c = 0; c < 16; c++) {
        size_t off = ((size_t)((b*16 + c)*NH + h)*DH + p)*NS + n;
        g_prev[off] = s;
        float dec = __expf(g_dacs[(size_t)(b*L_ + c*CK + CK - 1)*NH + h]);
        s = s * dec + g_states[off];
    }
}

// ---------------- fused y = y_diag + y_off + Dp*x per (chunk, head) ----------------
#define Y_SMEM_BYTES ((256*64 + 128*68 + 256*36 + 256 + 256) * 4)
__global__ __launch_bounds__(256) void y_kernel(const float* __restrict__ Dp)
{
    extern __shared__ float sm[];
    float* xs    = sm;                      // [256][64]
    float* prevT = xs + 256*64;             // [128][68]  (n-major, padded)
    float* Cs    = prevT + 128*68;          // [256][36]  (32-col tile, padded)
    float* das   = Cs + 256*36;             // [256]
    float* dts   = das + 256;               // [256]

    int chunk = blockIdx.x;
    int h = blockIdx.y;
    int base = chunk * CK;
    int tid = threadIdx.x;

    // balanced warp->row-block mapping: SMSP s gets blocks {2s, 7-2s}
    int w = tid >> 5, lane = tid & 31;
    int rb = (w < 4) ? (2*w) : (7 - 2*(w - 4));
    int i = rb*32 + lane;

    // loads
    {
        const float4* src = (const float4*)&g_xBC[(size_t)(base + i)*CD + h*64];
        float4* dst = (float4*)&xs[i*64];
#pragma unroll
        for (int q = 0; q < 16; q++) dst[q] = src[q];
    }
    das[i] = g_dacs[(base + i)*NH + h];
    dts[i] = g_dt[(base + i)*NH + h];
    {
        size_t pb = (size_t)(chunk*NH + h) * DH * NS;
#pragma unroll
        for (int e = 0; e < 32; e++) {
            int f = tid + e*256;       // 0..8191
            int p = f >> 7, n = f & 127;
            prevT[n*68 + p] = g_prev[pb + f];
        }
    }
    __syncthreads();

    float dai = das[i];
    float dph = Dp[h];
    float acc[64];
    {
        const float4* xr = (const float4*)&xs[i*64];
#pragma unroll
        for (int q = 0; q < 16; q++) {
            float4 v = xr[q];
            acc[4*q+0] = dph*v.x; acc[4*q+1] = dph*v.y;
            acc[4*q+2] = dph*v.z; acc[4*q+3] = dph*v.w;
        }
    }

    // phase A: y_diag (causal, j <= i)
    const float* cb = g_CBt + (size_t)chunk * CK * CK;
    for (int j = 0; j <= i; j++) {
        float wgt = cb[j*CK + i] * __expf(dai - das[j]) * dts[j];
        const float4* xr = (const float4*)&xs[j*64];
#pragma unroll
        for (int q = 0; q < 16; q++) {
            float4 v = xr[q];
            acc[4*q+0] += wgt*v.x; acc[4*q+1] += wgt*v.y;
            acc[4*q+2] += wgt*v.z; acc[4*q+3] += wgt*v.w;
        }
    }

    // phase B: y_off = exp(dacs_i) * sum_n C[i][n] * prev[p][n]
    float ei = __expf(dai);
    for (int nt = 0; nt < 4; nt++) {
        {
            const float4* src = (const float4*)&g_xBC[(size_t)(base + i)*CD + DI + NS + nt*32];
            float4* dst = (float4*)&Cs[i*36];
#pragma unroll
            for (int q = 0; q < 8; q++) dst[q] = src[q];
        }
        __syncthreads();
        for (int nn = 0; nn < 32; nn++) {
            float cv = ei * Cs[i*36 + nn];
            const float4* pr = (const float4*)&prevT[(nt*32 + nn)*68];
#pragma unroll
            for (int q = 0; q < 16; q++) {
                float4 v = pr[q];
                acc[4*q+0] += cv*v.x; acc[4*q+1] += cv*v.y;
                acc[4*q+2] += cv*v.z; acc[4*q+3] += cv*v.w;
            }
        }
        __syncthreads();
    }

    {
        float4* dst = (float4*)&g_y[(size_t)(base + i)*DI + h*64];
#pragma unroll
        for (int q = 0; q < 16; q++)
            dst[q] = make_float4(acc[4*q], acc[4*q+1], acc[4*q+2], acc[4*q+3]);
    }
}

// ---------------- gate (silu(z)) + RMSNorm ----------------
__global__ __launch_bounds__(256) void gate_norm_kernel(const float* __restrict__ norm_w)
{
    __shared__ float buf[DI];
    __shared__ float red[8];
    int r = blockIdx.x;
    int tid = threadIdx.x;
    float ss = 0.f;
#pragma unroll
    for (int e = 0; e < 16; e++) {
        int c = tid + e*256;
        float y = g_y[(size_t)r*DI + c];
        float z = g_zx[(size_t)r*DPJ + c];
        float g = y * (z / (1.f + __expf(-z)));
        buf[c] = g;
        ss += g*g;
    }
#pragma unroll
    for (int o = 16; o > 0; o >>= 1) ss += __shfl_xor_sync(0xffffffffu, ss, o);
    if ((tid & 31) == 0) red[tid >> 5] = ss;
    __syncthreads();
    float tot = 0.f;
#pragma unroll
    for (int q = 0; q < 8; q++) tot += red[q];
    float scale = rsqrtf(tot / (float)DI + 1e-5f);
#pragma unroll
    for (int e = 0; e < 16; e++) {
        int c = tid + e*256;
        g_y[(size_t)r*DI + c] = buf[c] * scale * norm_w[c];
    }
}

// ---------------- launch ----------------
extern "C" void kernel_launch(void* const* d_in, const int* in_sizes, int n_in,
                              void* d_out, int out_size)
{
    const float* u       = (const float*)d_in[0];
    const float* W_in    = (const float*)d_in[1];
    const float* conv_w  = (const float*)d_in[2];
    const float* conv_b  = (const float*)d_in[3];
    const float* dt_bias = (const float*)d_in[4];
    const float* A_log   = (const float*)d_in[5];
    const float* Dp      = (const float*)d_in[6];
    const float* norm_w  = (const float*)d_in[7];
    const float* W_out   = (const float*)d_in[8];
    float* out = (float*)d_out;

    float *zx, *xbc, *cbt, *y;
    cudaGetSymbolAddress((void**)&zx,  g_zx);
    cudaGetSymbolAddress((void**)&xbc, g_xBC);
    cudaGetSymbolAddress((void**)&cbt, g_CBt);
    cudaGetSymbolAddress((void**)&y,   g_y);

    cudaFuncSetAttribute(y_kernel, cudaFuncAttributeMaxDynamicSharedMemorySize, Y_SMEM_BYTES);

    // 1) in-proj: zx[8192,8512] = u[8192,2048] @ W_in[8512,2048]^T
    dim3 g1((DPJ + 127)/128, RW/128, 1);
    sgemm_nt<<<g1, 256>>>(u, W_in, zx, RW, DPJ, DM, DM, DM, DPJ, 0, 0, 0);

    // 2) conv + silu
    conv_silu_kernel<<<dim3(CD/256, RW), 256>>>(conv_w, conv_b);

    // 3) dt softplus + cumsum
    dt_cumsum_kernel<<<NCH, 64>>>(dt_bias, A_log);

    // 4) per-chunk CBt[j][i] = sum_n B[j,n]*C[i,n]  (batched over 32 chunks)
    dim3 g2(2, 2, NCH);
    sgemm_nt<<<g2, 256>>>(xbc + DI, xbc + DI + NS, cbt,
                          CK, CK, NS, CD, CD, CK,
                          (long)CK*CD, (long)CK*CD, (long)CK*CK);

    // 5) per-(chunk,head) states
    states_kernel<<<dim3(NCH, NH), 256>>>();

    // 6) inter-chunk scan
    scan_kernel<<<4096, 256>>>();

    // 7) fused y = y_diag + y_off + Dp*x
    y_kernel<<<dim3(NCH, NH), 256, Y_SMEM_BYTES>>>(Dp);

    // 8) gate + RMSNorm
    gate_norm_kernel<<<RW, 256>>>(norm_w);

    // 9) out-proj: out[8192,2048] = y[8192,4096] @ W_out[2048,4096]^T
    dim3 g3(DM/128, RW/128, 1);
    sgemm_nt<<<g3, 256>>>(y, W_out, out, RW, DM, DI, DI, DI, DM, 0, 0, 0);
}

// round 4
// speedup vs baseline: 1.9565x; 1.9565x over previous
#include <cuda_runtime.h>
#include <cuda_bf16.h>
#include <math.h>
#include <stdint.h>

// ---------------- problem constants ----------------
#define L_   4096
#define DM   2048          // D_MODEL
#define DI   4096          // D_INNER
#define NH   64            // N_HEADS
#define DH   64            // D_HEAD
#define NS   128           // D_STATE
#define CD   4352          // CONV_DIM
#define DPJ  8512          // D_IN_PROJ
#define DPJA 8704          // padded to 68*128 for GEMM tiles
#define CK   256           // CHUNK
#define NCH  32            // total chunks
#define RW   8192          // total rows = B*L

// ---------------- scratch (device globals; no allocations) ----------------
__device__ float g_zx[(size_t)RW * DPJA];
__device__ float g_xBC[(size_t)RW * CD];
__device__ float g_dt[RW * NH];
__device__ float g_dacs[RW * NH];
__device__ float g_CBt[NCH * CK * CK];
__device__ float g_states[(size_t)NCH * NH * DH * NS];
__device__ float g_prev[(size_t)NCH * NH * DH * NS];
__device__ float g_y[(size_t)RW * DI];
// split-bf16 operands
__device__ __nv_bfloat16 g_uh[(size_t)RW * DM],  g_ul[(size_t)RW * DM];
__device__ __nv_bfloat16 g_wih[(size_t)DPJA * DM], g_wil[(size_t)DPJA * DM];
__device__ __nv_bfloat16 g_yh[(size_t)RW * DI],  g_yl[(size_t)RW * DI];
__device__ __nv_bfloat16 g_woh[(size_t)DM * DI], g_wol[(size_t)DM * DI];

// ================= PTX helpers (portable, compute_103-safe) =================
__device__ __forceinline__ uint32_t smem_u32(const void* p) {
    uint32_t a;
    asm("{ .reg .u64 t; cvta.to.shared.u64 t, %1; cvt.u32.u64 %0, t; }" : "=r"(a) : "l"(p));
    return a;
}
#define CPA16(dst, src) \
    asm volatile("cp.async.cg.shared.global [%0], [%1], 16;" :: "r"(dst), "l"(src) : "memory")

#define LDSM4(r, adr)                                                            \
    asm volatile("ldmatrix.sync.aligned.m8n8.x4.shared.b16 {%0,%1,%2,%3}, [%4];" \
        : "=r"((r)[0]), "=r"((r)[1]), "=r"((r)[2]), "=r"((r)[3]) : "r"(adr))

#define MMA16816(c, a, b0, b1)                                                   \
    asm volatile("mma.sync.aligned.m16n8k16.row.col.f32.bf16.bf16.f32 "          \
        "{%0,%1,%2,%3}, {%4,%5,%6,%7}, {%8,%9}, {%0,%1,%2,%3};"                  \
        : "+f"((c)[0]), "+f"((c)[1]), "+f"((c)[2]), "+f"((c)[3])                  \
        : "r"((a)[0]), "r"((a)[1]), "r"((a)[2]), "r"((a)[3]), "r"(b0), "r"(b1))

// ================= split fp32 -> (hi, lo) bf16 =================
__global__ __launch_bounds__(256) void split_kernel(
    const float* __restrict__ src, __nv_bfloat16* __restrict__ hi,
    __nv_bfloat16* __restrict__ lo, long n4)
{
    long i = (long)blockIdx.x * 256 + threadIdx.x;
    if (i >= n4) return;
    float4 v = ((const float4*)src)[i];
    __nv_bfloat16 h0 = __float2bfloat16(v.x), h1 = __float2bfloat16(v.y);
    __nv_bfloat16 h2 = __float2bfloat16(v.z), h3 = __float2bfloat16(v.w);
    __nv_bfloat16 l0 = __float2bfloat16(v.x - __bfloat162float(h0));
    __nv_bfloat16 l1 = __float2bfloat16(v.y - __bfloat162float(h1));
    __nv_bfloat16 l2 = __float2bfloat16(v.z - __bfloat162float(h2));
    __nv_bfloat16 l3 = __float2bfloat16(v.w - __bfloat162float(h3));
    ((__nv_bfloat162*)hi)[2*i]   = __nv_bfloat162(h0, h1);
    ((__nv_bfloat162*)hi)[2*i+1] = __nv_bfloat162(h2, h3);
    ((__nv_bfloat162*)lo)[2*i]   = __nv_bfloat162(l0, l1);
    ((__nv_bfloat162*)lo)[2*i+1] = __nv_bfloat162(l2, l3);
}

// padded variant: rows >= rows_src are zero (cols4 = cols/4)
__global__ __launch_bounds__(256) void split_pad_kernel(
    const float* __restrict__ src, __nv_bfloat16* __restrict__ hi,
    __nv_bfloat16* __restrict__ lo, long n4, long rows_src, long cols4)
{
    long i = (long)blockIdx.x * 256 + threadIdx.x;
    if (i >= n4) return;
    float4 v = make_float4(0.f, 0.f, 0.f, 0.f);
    if (i / cols4 < rows_src) v = ((const float4*)src)[i];
    __nv_bfloat16 h0 = __float2bfloat16(v.x), h1 = __float2bfloat16(v.y);
    __nv_bfloat16 h2 = __float2bfloat16(v.z), h3 = __float2bfloat16(v.w);
    __nv_bfloat16 l0 = __float2bfloat16(v.x - __bfloat162float(h0));
    __nv_bfloat16 l1 = __float2bfloat16(v.y - __bfloat162float(h1));
    __nv_bfloat16 l2 = __float2bfloat16(v.z - __bfloat162float(h2));
    __nv_bfloat16 l3 = __float2bfloat16(v.w - __bfloat162float(h3));
    ((__nv_bfloat162*)hi)[2*i]   = __nv_bfloat162(h0, h1);
    ((__nv_bfloat162*)hi)[2*i+1] = __nv_bfloat162(h2, h3);
    ((__nv_bfloat162*)lo)[2*i]   = __nv_bfloat162(l0, l1);
    ((__nv_bfloat162*)lo)[2*i+1] = __nv_bfloat162(l2, l3);
}

// ================= mma.sync split-bf16 NT GEMM =================
// C[m][n] = sum_k A[m][k]*B[n][k]; A = Ah+Al, B = Bh+Bl; products Ah.Bh + Ah.Bl + Al.Bh.
// CTA tile 128x128, K-step 32, 2-stage cp.async pipeline.
// smem tile: [128 rows][40 bf16] (stride 40 elems = 80B -> conflict-free ldmatrix).
#define GT_ROWSTRIDE 40
#define GT_TILE (128 * GT_ROWSTRIDE)          // elems per tile
#define GT_STAGE (4 * GT_TILE)                // Ah, Al, Bh, Bl
#define GEMM_SMEM (2 * GT_STAGE * 2)          // bytes (2 stages, bf16)

__global__ __launch_bounds__(256) void gemm_mma(
    const __nv_bfloat16* __restrict__ Ah, const __nv_bfloat16* __restrict__ Al,
    const __nv_bfloat16* __restrict__ Bh, const __nv_bfloat16* __restrict__ Bl,
    float* __restrict__ C, int Ktot, int ldc)
{
    extern __shared__ __nv_bfloat16 smem[];
    const int tid = threadIdx.x;
    const int wid = tid >> 5;
    const int lane = tid & 31;

    const int m0 = blockIdx.y * 128;
    const int n0 = blockIdx.x * 128;

    const int lr0 = tid >> 2;            // rows 0..63
    const int lc  = (tid & 3) * 8;       // bf16 col offset (16B chunks)

    const __nv_bfloat16* arh = Ah + (size_t)m0 * Ktot;
    const __nv_bfloat16* arl = Al + (size_t)m0 * Ktot;
    const __nv_bfloat16* brh = Bh + (size_t)n0 * Ktot;
    const __nv_bfloat16* brl = Bl + (size_t)n0 * Ktot;

    auto load_stage = [&](int s, int k0) {
        __nv_bfloat16* st = smem + s * GT_STAGE;
#pragma unroll
        for (int q = 0; q < 2; q++) {
            int row = lr0 + q * 64;
            uint32_t d = smem_u32(st + row * GT_ROWSTRIDE + lc);
            const char* sa_h = (const char*)(arh + (size_t)row * Ktot + k0 + lc);
            const char* sa_l = (const char*)(arl + (size_t)row * Ktot + k0 + lc);
            const char* sb_h = (const char*)(brh + (size_t)row * Ktot + k0 + lc);
            const char* sb_l = (const char*)(brl + (size_t)row * Ktot + k0 + lc);
            CPA16(d, sa_h);
            CPA16(d + GT_TILE * 2, sa_l);
            CPA16(d + GT_TILE * 4, sb_h);
            CPA16(d + GT_TILE * 6, sb_l);
        }
        asm volatile("cp.async.commit_group;" ::: "memory");
    };

    // warp tiling: 2 warps along M (64 rows each), 4 along N (32 cols each)
    const int wm = (wid & 1) * 64;
    const int wn = (wid >> 1) * 32;
    const int fr = lane & 15;            // ldmatrix row within 16
    const int fc = (lane >> 4) * 8;      // ldmatrix col half

    float acc[4][4][4];
#pragma unroll
    for (int a = 0; a < 4; a++)
#pragma unroll
        for (int b = 0; b < 4; b++)
#pragma unroll
            for (int c = 0; c < 4; c++) acc[a][b][c] = 0.f;

    const int KT = Ktot / 32;
    load_stage(0, 0);

    for (int kt = 0; kt < KT; kt++) {
        const int cur = kt & 1;
        if (kt + 1 < KT) {
            load_stage(cur ^ 1, (kt + 1) * 32);
            asm volatile("cp.async.wait_group 1;" ::: "memory");
        } else {
            asm volatile("cp.async.wait_group 0;" ::: "memory");
        }
        __syncthreads();

        const __nv_bfloat16* st = smem + cur * GT_STAGE;
#pragma unroll
        for (int kk = 0; kk < 2; kk++) {
            const int kof = kk * 16;
            uint32_t ah[4][4], al[4][4];
#pragma unroll
            for (int mb = 0; mb < 4; mb++) {
                uint32_t adr = smem_u32(st + (wm + mb * 16 + fr) * GT_ROWSTRIDE + kof + fc);
                LDSM4(ah[mb], adr);
                LDSM4(al[mb], adr + GT_TILE * 2);
            }
            uint32_t bh[2][4], bl[2][4];
#pragma unroll
            for (int nb2 = 0; nb2 < 2; nb2++) {
                uint32_t adr = smem_u32(st + 2 * GT_TILE +
                                        (wn + nb2 * 16 + fr) * GT_ROWSTRIDE + kof + fc);
                LDSM4(bh[nb2], adr);
                LDSM4(bl[nb2], adr + GT_TILE * 2);
            }
#pragma unroll
            for (int mb = 0; mb < 4; mb++)
#pragma unroll
                for (int nb = 0; nb < 4; nb++)
                    MMA16816(acc[mb][nb], ah[mb], bh[nb >> 1][nb & 1], bh[nb >> 1][(nb & 1) + 2]);
#pragma unroll
            for (int mb = 0; mb < 4; mb++)
#pragma unroll
                for (int nb = 0; nb < 4; nb++)
                    MMA16816(acc[mb][nb], ah[mb], bl[nb >> 1][nb & 1], bl[nb >> 1][(nb & 1) + 2]);
#pragma unroll
            for (int mb = 0; mb < 4; mb++)
#pragma unroll
                for (int nb = 0; nb < 4; nb++)
                    MMA16816(acc[mb][nb], al[mb], bh[nb >> 1][nb & 1], bh[nb >> 1][(nb & 1) + 2]);
        }
        __syncthreads();
    }

    const int er = lane >> 2;
    const int ec = (lane & 3) * 2;
#pragma unroll
    for (int mb = 0; mb < 4; mb++) {
#pragma unroll
        for (int nb = 0; nb < 4; nb++) {
            float* p0 = C + (size_t)(m0 + wm + mb * 16 + er) * ldc + n0 + wn + nb * 8 + ec;
            float* p1 = p0 + 8 * ldc;
            *(float2*)p0 = make_float2(acc[mb][nb][0], acc[mb][nb][1]);
            *(float2*)p1 = make_float2(acc[mb][nb][2], acc[mb][nb][3]);
        }
    }
}

// ---------------- fp32 NT SGEMM (kept for small per-chunk C@B^T) ----------------
__global__ __launch_bounds__(256) void sgemm_nt(
    const float* __restrict__ A, const float* __restrict__ Bm, float* __restrict__ C,
    int M, int N, int K, int lda, int ldb, int ldc,
    long sA, long sB, long sC)
{
    const float* Ab = A + (long)blockIdx.z * sA;
    const float* Bb = Bm + (long)blockIdx.z * sB;
    float* Cb = C + (long)blockIdx.z * sC;

    __shared__ float As[16][128];
    __shared__ float Bs[16][128];

    const int tid = threadIdx.x;
    const int m0 = blockIdx.y * 128;
    const int n0 = blockIdx.x * 128;
    const int tx = tid & 15;
    const int ty = tid >> 4;

    const int lrow = tid >> 1;
    const int lk = (tid & 1) * 8;
    const float* Aload = Ab + (long)(m0 + lrow) * lda + lk;
    const float* Bload = Bb + (long)(n0 + lrow) * ldb + lk;
    const bool bvalid = (n0 + lrow) < N;

    float acc[8][8];
#pragma unroll
    for (int i = 0; i < 8; i++)
#pragma unroll
        for (int j = 0; j < 8; j++) acc[i][j] = 0.0f;

    float4 a0 = *(const float4*)(Aload);
    float4 a1 = *(const float4*)(Aload + 4);
    float4 b0 = make_float4(0.f,0.f,0.f,0.f), b1 = make_float4(0.f,0.f,0.f,0.f);
    if (bvalid) { b0 = *(const float4*)(Bload); b1 = *(const float4*)(Bload + 4); }

    for (int k0 = 0; k0 < K; k0 += 16) {
        As[lk+0][lrow] = a0.x; As[lk+1][lrow] = a0.y; As[lk+2][lrow] = a0.z; As[lk+3][lrow] = a0.w;
        As[lk+4][lrow] = a1.x; As[lk+5][lrow] = a1.y; As[lk+6][lrow] = a1.z; As[lk+7][lrow] = a1.w;
        Bs[lk+0][lrow] = b0.x; Bs[lk+1][lrow] = b0.y; Bs[lk+2][lrow] = b0.z; Bs[lk+3][lrow] = b0.w;
        Bs[lk+4][lrow] = b1.x; Bs[lk+5][lrow] = b1.y; Bs[lk+6][lrow] = b1.z; Bs[lk+7][lrow] = b1.w;
        __syncthreads();
        if (k0 + 16 < K) {
            a0 = *(const float4*)(Aload + k0 + 16);
            a1 = *(const float4*)(Aload + k0 + 20);
            if (bvalid) {
                b0 = *(const float4*)(Bload + k0 + 16);
                b1 = *(const float4*)(Bload + k0 + 20);
            }
        }
#pragma unroll
        for (int kk = 0; kk < 16; kk++) {
            float av[8], bv[8];
            *(float4*)&av[0] = *(const float4*)&As[kk][ty*8];
            *(float4*)&av[4] = *(const float4*)&As[kk][ty*8+4];
            *(float4*)&bv[0] = *(const float4*)&Bs[kk][tx*8];
            *(float4*)&bv[4] = *(const float4*)&Bs[kk][tx*8+4];
#pragma unroll
            for (int i = 0; i < 8; i++)
#pragma unroll
                for (int j = 0; j < 8; j++) acc[i][j] += av[i]*bv[j];
        }
        __syncthreads();
    }

#pragma unroll
    for (int i = 0; i < 8; i++) {
        int row = m0 + ty*8 + i;
        float* Crow = Cb + (long)row*ldc + n0 + tx*8;
        if (n0 + tx*8 + 4 <= N) {
            *(float4*)Crow = make_float4(acc[i][0],acc[i][1],acc[i][2],acc[i][3]);
        }
        if (n0 + tx*8 + 8 <= N) {
            *(float4*)(Crow+4) = make_float4(acc[i][4],acc[i][5],acc[i][6],acc[i][7]);
        }
    }
}

// ---------------- causal depthwise conv (width 4) + SiLU ----------------
__global__ void conv_silu_kernel(const float* __restrict__ conv_w,
                                 const float* __restrict__ conv_b)
{
    int cc = blockIdx.x * 256 + threadIdx.x;
    int r = blockIdx.y;
    int l = r & (L_ - 1);
    float acc = conv_b[cc];
    const float* col = g_zx + (size_t)r * DPJA + DI + cc;
#pragma unroll
    for (int w = 0; w < 4; w++) {
        int lp = l - 3 + w;
        if (lp >= 0) acc += col[(long)(w - 3) * DPJA] * conv_w[cc*4 + w];
    }
    float s = acc / (1.0f + __expf(-acc));
    g_xBC[(size_t)r * CD + cc] = s;
}

// ---------------- dt softplus + within-chunk cumsum of dt*A ----------------
__global__ void dt_cumsum_kernel(const float* __restrict__ dt_bias,
                                 const float* __restrict__ A_log)
{
    int h = threadIdx.x;
    int chunk = blockIdx.x;
    int base = chunk * CK;
    float Ah = -expf(A_log[h]);
    float bh = dt_bias[h];
    float acc = 0.f;
    for (int i = 0; i < CK; i++) {
        int r = base + i;
        float x = g_zx[(size_t)r * DPJA + DI + CD + h] + bh;
        float dt = fmaxf(x, 0.f) + log1pf(expf(-fabsf(x)));
        g_dt[r*NH + h] = dt;
        acc += dt * Ah;
        g_dacs[r*NH + h] = acc;
    }
}

// ---------------- per-(chunk,head) state accumulation ----------------
__global__ __launch_bounds__(256) void states_kernel()
{
    int chunk = blockIdx.x;
    int h = blockIdx.y;
    int base = chunk * CK;
    int tid = threadIdx.x;

    __shared__ float ws[CK];
    __shared__ float xs[32*64];
    __shared__ float Bsh[32*128];

    {
        float dl = g_dacs[(base + CK - 1)*NH + h];
        float dv = g_dacs[(base + tid)*NH + h];
        ws[tid] = __expf(dl - dv) * g_dt[(base + tid)*NH + h];
    }

    const int tp = tid >> 5;
    const int tn = tid & 31;
    float acc[8][4];
#pragma unroll
    for (int a = 0; a < 8; a++)
#pragma unroll
        for (int b = 0; b < 4; b++) acc[a][b] = 0.f;

    for (int st = 0; st < 8; st++) {
        __syncthreads();
#pragma unroll
        for (int rep = 0; rep < 2; rep++) {
            int f = tid + rep*256;
            int row = f >> 4, c4 = f & 15;
            *(float4*)&xs[row*64 + c4*4] =
                *(const float4*)&g_xBC[(size_t)(base + st*32 + row)*CD + h*64 + c4*4];
        }
#pragma unroll
        for (int rep = 0; rep < 4; rep++) {
            int f = tid + rep*256;
            int row = f >> 5, c4 = f & 31;
            *(float4*)&Bsh[row*128 + c4*4] =
                *(const float4*)&g_xBC[(size_t)(base + st*32 + row)*CD + DI + c4*4];
        }
        __syncthreads();

        for (int s = 0; s < 32; s++) {
            float w = ws[st*32 + s];
            float4 bv = *(const float4*)&Bsh[s*128 + tn*4];
            float xw[8];
#pragma unroll
            for (int pp = 0; pp < 8; pp++) xw[pp] = w * xs[s*64 + tp + pp*8];
#pragma unroll
            for (int pp = 0; pp < 8; pp++) {
                acc[pp][0] += xw[pp]*bv.x;
                acc[pp][1] += xw[pp]*bv.y;
                acc[pp][2] += xw[pp]*bv.z;
                acc[pp][3] += xw[pp]*bv.w;
            }
        }
    }

    size_t obase = (size_t)(chunk*NH + h) * DH * NS;
#pragma unroll
    for (int pp = 0; pp < 8; pp++) {
        *(float4*)&g_states[obase + (size_t)(tp + pp*8)*NS + tn*4] =
            make_float4(acc[pp][0], acc[pp][1], acc[pp][2], acc[pp][3]);
    }
}

// ---------------- inter-chunk scan ----------------
__global__ void scan_kernel()
{
    int idx = blockIdx.x * 256 + threadIdx.x;
    int h = (idx >> 13) & 63;
    int b = idx >> 19;
    float s = 0.f;
    for (int c = 0; c < 16; c++) {
        size_t off = ((size_t)(b*16 + c)*NH + h)*DH*NS + (idx & 8191);
        g_prev[off] = s;
        float dec = __expf(g_dacs[(size_t)(b*L_ + c*CK + CK - 1)*NH + h]);
        s = s * dec + g_states[off];
    }
}

// ---------------- fused y = y_diag + y_off + Dp*x per (chunk, head) ----------------
#define Y_SMEM_BYTES ((256*64 + 128*68 + 256*36 + 256 + 256) * 4)
__global__ __launch_bounds__(256) void y_kernel(const float* __restrict__ Dp)
{
    extern __shared__ float sm[];
    float* xs    = sm;
    float* prevT = xs + 256*64;
    float* Cs    = prevT + 128*68;
    float* das   = Cs + 256*36;
    float* dts   = das + 256;

    int chunk = blockIdx.x;
    int h = blockIdx.y;
    int base = chunk * CK;
    int tid = threadIdx.x;

    int w = tid >> 5, lane = tid & 31;
    int rb = (w < 4) ? (2*w) : (7 - 2*(w - 4));
    int i = rb*32 + lane;

    {
        const float4* src = (const float4*)&g_xBC[(size_t)(base + i)*CD + h*64];
        float4* dst = (float4*)&xs[i*64];
#pragma unroll
        for (int q = 0; q < 16; q++) dst[q] = src[q];
    }
    das[i] = g_dacs[(base + i)*NH + h];
    dts[i] = g_dt[(base + i)*NH + h];
    {
        size_t pb = (size_t)(chunk*NH + h) * DH * NS;
#pragma unroll
        for (int e = 0; e < 32; e++) {
            int f = tid + e*256;
            int p = f >> 7, n = f & 127;
            prevT[n*68 + p] = g_prev[pb + f];
        }
    }
    __syncthreads();

    float dai = das[i];
    float dph = Dp[h];
    float acc[64];
    {
        const float4* xr = (const float4*)&xs[i*64];
#pragma unroll
        for (int q = 0; q < 16; q++) {
            float4 v = xr[q];
            acc[4*q+0] = dph*v.x; acc[4*q+1] = dph*v.y;
            acc[4*q+2] = dph*v.z; acc[4*q+3] = dph*v.w;
        }
    }

    const float* cb = g_CBt + (size_t)chunk * CK * CK;
    for (int j = 0; j <= i; j++) {
        float wgt = cb[j*CK + i] * __expf(dai - das[j]) * dts[j];
        const float4* xr = (const float4*)&xs[j*64];
#pragma unroll
        for (int q = 0; q < 16; q++) {
            float4 v = xr[q];
            acc[4*q+0] += wgt*v.x; acc[4*q+1] += wgt*v.y;
            acc[4*q+2] += wgt*v.z; acc[4*q+3] += wgt*v.w;
        }
    }

    float ei = __expf(dai);
    for (int nt = 0; nt < 4; nt++) {
        {
            const float4* src = (const float4*)&g_xBC[(size_t)(base + i)*CD + DI + NS + nt*32];
            float4* dst = (float4*)&Cs[i*36];
#pragma unroll
            for (int q = 0; q < 8; q++) dst[q] = src[q];
        }
        __syncthreads();
        for (int nn = 0; nn < 32; nn++) {
            float cv = ei * Cs[i*36 + nn];
            const float4* pr = (const float4*)&prevT[(nt*32 + nn)*68];
#pragma unroll
            for (int q = 0; q < 16; q++) {
                float4 v = pr[q];
                acc[4*q+0] += cv*v.x; acc[4*q+1] += cv*v.y;
                acc[4*q+2] += cv*v.z; acc[4*q+3] += cv*v.w;
            }
        }
        __syncthreads();
    }

    {
        float4* dst = (float4*)&g_y[(size_t)(base + i)*DI + h*64];
#pragma unroll
        for (int q = 0; q < 16; q++)
            dst[q] = make_float4(acc[4*q], acc[4*q+1], acc[4*q+2], acc[4*q+3]);
    }
}

// ---------------- gate (silu(z)) + RMSNorm ----------------
__global__ __launch_bounds__(256) void gate_norm_kernel(const float* __restrict__ norm_w)
{
    __shared__ float buf[DI];
    __shared__ float red[8];
    int r = blockIdx.x;
    int tid = threadIdx.x;
    float ss = 0.f;
#pragma unroll
    for (int e = 0; e < 16; e++) {
        int c = tid + e*256;
        float y = g_y[(size_t)r*DI + c];
        float z = g_zx[(size_t)r*DPJA + c];
        float g = y * (z / (1.f + __expf(-z)));
        buf[c] = g;
        ss += g*g;
    }
#pragma unroll
    for (int o = 16; o > 0; o >>= 1) ss += __shfl_xor_sync(0xffffffffu, ss, o);
    if ((tid & 31) == 0) red[tid >> 5] = ss;
    __syncthreads();
    float tot = 0.f;
#pragma unroll
    for (int q = 0; q < 8; q++) tot += red[q];
    float scale = rsqrtf(tot / (float)DI + 1e-5f);
#pragma unroll
    for (int e = 0; e < 16; e++) {
        int c = tid + e*256;
        g_y[(size_t)r*DI + c] = buf[c] * scale * norm_w[c];
    }
}

// ---------------- launch ----------------
extern "C" void kernel_launch(void* const* d_in, const int* in_sizes, int n_in,
                              void* d_out, int out_size)
{
    const float* u       = (const float*)d_in[0];
    const float* W_in    = (const float*)d_in[1];
    const float* conv_w  = (const float*)d_in[2];
    const float* conv_b  = (const float*)d_in[3];
    const float* dt_bias = (const float*)d_in[4];
    const float* A_log   = (const float*)d_in[5];
    const float* Dp      = (const float*)d_in[6];
    const float* norm_w  = (const float*)d_in[7];
    const float* W_out   = (const float*)d_in[8];
    float* out = (float*)d_out;

    float *zx, *xbc, *cbt, *y;
    __nv_bfloat16 *uh, *ul, *wih, *wil, *yh, *yl, *woh, *wol;
    cudaGetSymbolAddress((void**)&zx,  g_zx);
    cudaGetSymbolAddress((void**)&xbc, g_xBC);
    cudaGetSymbolAddress((void**)&cbt, g_CBt);
    cudaGetSymbolAddress((void**)&y,   g_y);
    cudaGetSymbolAddress((void**)&uh,  g_uh);
    cudaGetSymbolAddress((void**)&ul,  g_ul);
    cudaGetSymbolAddress((void**)&wih, g_wih);
    cudaGetSymbolAddress((void**)&wil, g_wil);
    cudaGetSymbolAddress((void**)&yh,  g_yh);
    cudaGetSymbolAddress((void**)&yl,  g_yl);
    cudaGetSymbolAddress((void**)&woh, g_woh);
    cudaGetSymbolAddress((void**)&wol, g_wol);

    cudaFuncSetAttribute(y_kernel, cudaFuncAttributeMaxDynamicSharedMemorySize, Y_SMEM_BYTES);
    cudaFuncSetAttribute(gemm_mma, cudaFuncAttributeMaxDynamicSharedMemorySize, GEMM_SMEM);

    // split inputs for GEMM1
    {
        long n4 = (long)RW * DM / 4;
        split_kernel<<<(int)((n4 + 255) / 256), 256>>>(u, uh, ul, n4);
    }
    {
        long n4 = (long)DPJA * DM / 4;
        split_pad_kernel<<<(int)((n4 + 255) / 256), 256>>>(W_in, wih, wil, n4, DPJ, DM/4);
    }

    // 1) in-proj: zx[8192, 8704(pad)] = u @ W_in^T  (mma.sync split-bf16 3-pass)
    gemm_mma<<<dim3(DPJA/128, RW/128), 256, GEMM_SMEM>>>(uh, ul, wih, wil, zx, DM, DPJA);

    // 2) conv + silu
    conv_silu_kernel<<<dim3(CD/256, RW), 256>>>(conv_w, conv_b);

    // 3) dt softplus + cumsum
    dt_cumsum_kernel<<<NCH, 64>>>(dt_bias, A_log);

    // 4) per-chunk CBt
    dim3 g2(2, 2, NCH);
    sgemm_nt<<<g2, 256>>>(xbc + DI, xbc + DI + NS, cbt,
                          CK, CK, NS, CD, CD, CK,
                          (long)CK*CD, (long)CK*CD, (long)CK*CK);

    // 5) states
    states_kernel<<<dim3(NCH, NH), 256>>>();

    // 6) inter-chunk scan
    scan_kernel<<<4096, 256>>>();

    // 7) fused y
    y_kernel<<<dim3(NCH, NH), 256, Y_SMEM_BYTES>>>(Dp);

    // 8) gate + RMSNorm
    gate_norm_kernel<<<RW, 256>>>(norm_w);

    // split for GEMM2
    {
        long n4 = (long)RW * DI / 4;
        split_kernel<<<(int)((n4 + 255) / 256), 256>>>(y, yh, yl, n4);
    }
    {
        long n4 = (long)DM * DI / 4;
        split_kernel<<<(int)((n4 + 255) / 256), 256>>>(W_out, woh, wol, n4);
    }

    // 9) out-proj: out[8192,2048] = y @ W_out^T  (mma.sync)
    gemm_mma<<<dim3(DM/128, RW/128), 256, GEMM_SMEM>>>(yh, yl, woh, wol, out, DI, DM);
}